// round 2
// baseline (speedup 1.0000x reference)
#include <cuda_runtime.h>
#include <math.h>

#define N_NODES 200000
#define N_USERS 100000
#define DIM 64
#define E_MAX   1200000
#define NODES_PER_SCAN_BLK 1024
#define NUM_SCAN_BLOCKS ((N_NODES + NODES_PER_SCAN_BLK - 1) / NODES_PER_SCAN_BLK)  // 196

// ---- device scratch (static globals; no runtime allocation) ----
__device__ int   g_is64;
__device__ int   g_cnt[N_NODES];
__device__ int   g_off[N_NODES];
__device__ int   g_cur[N_NODES];
__device__ float g_dinv[N_NODES];
__device__ int   g_bsum[NUM_SCAN_BLOCKS];
__device__ int   g_bpre[NUM_SCAN_BLOCKS];
__device__ int   g_src[E_MAX];
__device__ float g_z[(size_t)N_NODES * DIM];   // (x@W)*dinv
__device__ float g_h[(size_t)N_NODES * DIM];   // layer-1 output

// robust index fetch: edge_index may be int64 or int32 depending on JAX x64 config
__device__ __forceinline__ int load_idx(const void* ei, size_t pos) {
    if (g_is64) return (int)((const long long*)ei)[pos];
    return ((const int*)ei)[pos];
}

// ------------------------------------------------------------------
// Detect dtype: if int64, high 32-bit word of every entry is 0 (indices < 2^31).
__global__ void k_detect(const unsigned int* __restrict__ raw) {
    __shared__ int any_hi;
    if (threadIdx.x == 0) any_hi = 0;
    __syncthreads();
    unsigned int hi = raw[threadIdx.x * 2 + 1];
    if (hi != 0u) any_hi = 1;           // benign race
    __syncthreads();
    if (threadIdx.x == 0) g_is64 = (any_hi == 0);
}

__global__ void k_zero() {
    int i = blockIdx.x * blockDim.x + threadIdx.x;
    if (i < N_NODES) g_cnt[i] = 0;
}

// in-degree histogram over col = edge_index[1]
__global__ void k_hist(const void* __restrict__ ei, int E) {
    int e = blockIdx.x * blockDim.x + threadIdx.x;
    if (e < E) {
        int c = load_idx(ei, (size_t)E + e);
        if ((unsigned)c < (unsigned)N_NODES) atomicAdd(&g_cnt[c], 1);
    }
}

// ---- prefix scan: block-local (256 thr x 4 nodes), then cross-block ----
__global__ __launch_bounds__(256) void k_scan1() {
    __shared__ int sbuf[2][256];
    int t = threadIdx.x;
    int base = blockIdx.x * NODES_PER_SCAN_BLK + t * 4;
    int v[4]; int sum = 0;
#pragma unroll
    for (int q = 0; q < 4; ++q) {
        v[q] = (base + q < N_NODES) ? g_cnt[base + q] : 0;
        sum += v[q];
    }
    sbuf[0][t] = sum;
    __syncthreads();
    int cur = 0;
#pragma unroll
    for (int d = 1; d < 256; d <<= 1) {
        int x = sbuf[cur][t];
        if (t >= d) x += sbuf[cur][t - d];
        sbuf[1 - cur][t] = x;
        cur ^= 1;
        __syncthreads();
    }
    int incl = sbuf[cur][t];
    int excl = incl - sum;
#pragma unroll
    for (int q = 0; q < 4; ++q) {
        if (base + q < N_NODES) g_off[base + q] = excl;
        excl += v[q];
    }
    if (t == 255) g_bsum[blockIdx.x] = incl;
}

__global__ __launch_bounds__(256) void k_scan2() {
    __shared__ int sbuf[2][256];
    int t = threadIdx.x;
    int val = (t < NUM_SCAN_BLOCKS) ? g_bsum[t] : 0;
    sbuf[0][t] = val;
    __syncthreads();
    int cur = 0;
#pragma unroll
    for (int d = 1; d < 256; d <<= 1) {
        int x = sbuf[cur][t];
        if (t >= d) x += sbuf[cur][t - d];
        sbuf[1 - cur][t] = x;
        cur ^= 1;
        __syncthreads();
    }
    if (t < NUM_SCAN_BLOCKS) g_bpre[t] = sbuf[cur][t] - val;
}

__global__ void k_scan3() {
    int idx = blockIdx.x * blockDim.x + threadIdx.x;
    if (idx < N_NODES) {
        int off = g_off[idx] + g_bpre[idx / NODES_PER_SCAN_BLK];
        g_off[idx] = off;
        g_cur[idx] = off;
        g_dinv[idx] = rsqrtf((float)(g_cnt[idx] + 1));  // +1 self-loop
    }
}

// scatter edge sources into dest-keyed CSR buckets
__global__ void k_fill(const void* __restrict__ ei, int E) {
    int e = blockIdx.x * blockDim.x + threadIdx.x;
    if (e < E) {
        int c = load_idx(ei, (size_t)E + e);
        int s = load_idx(ei, (size_t)e);
        if ((unsigned)c < (unsigned)N_NODES && (unsigned)s < (unsigned)N_NODES) {
            int p = atomicAdd(&g_cur[c], 1);
            g_src[p] = s;
        }
    }
}

// ------------------------------------------------------------------
// z[r,:] = (x[r,:] @ W) * dinv[r]
// src_mode 0: x = concat(user, item) split at N_USERS; 1: x = g_h
__global__ __launch_bounds__(256) void k_gemm(
    const float* __restrict__ xa, const float* __restrict__ xb,
    int src_mode, const float* __restrict__ W)
{
    __shared__ __align__(16) float Ws[64 * 64];
    __shared__ __align__(16) float xs[64][68];   // pad kills bank conflicts
    int tid = threadIdx.x;
    int block_row = blockIdx.x * 64;

    for (int i = tid; i < 1024; i += 256)
        ((float4*)Ws)[i] = ((const float4*)W)[i];

    {
        int r = tid >> 2;
        int kb = (tid & 3) * 16;
        int gr = block_row + r;
        const float* xrow;
        if (src_mode == 0)
            xrow = (gr < N_USERS) ? (xa + (size_t)gr * DIM)
                                  : (xb + (size_t)(gr - N_USERS) * DIM);
        else
            xrow = g_h + (size_t)gr * DIM;
#pragma unroll
        for (int q = 0; q < 4; ++q)
            *(float4*)(&xs[r][kb + q * 4]) = *(const float4*)(xrow + kb + q * 4);
    }
    __syncthreads();

    int ty = tid >> 4, tx = tid & 15;   // 4x4 micro-tile per thread
    float acc[4][4] = {};
#pragma unroll 16
    for (int k = 0; k < 64; ++k) {
        float4 wv = *(const float4*)(Ws + k * 64 + tx * 4);
#pragma unroll
        for (int i = 0; i < 4; ++i) {
            float xv = xs[ty * 4 + i][k];
            acc[i][0] = fmaf(xv, wv.x, acc[i][0]);
            acc[i][1] = fmaf(xv, wv.y, acc[i][1]);
            acc[i][2] = fmaf(xv, wv.z, acc[i][2]);
            acc[i][3] = fmaf(xv, wv.w, acc[i][3]);
        }
    }
#pragma unroll
    for (int i = 0; i < 4; ++i) {
        int gr = block_row + ty * 4 + i;
        float s = g_dinv[gr];
        float4 o = make_float4(acc[i][0] * s, acc[i][1] * s,
                               acc[i][2] * s, acc[i][3] * s);
        *(float4*)(g_z + (size_t)gr * DIM + tx * 4) = o;
    }
}

// ------------------------------------------------------------------
// out[c,:] = dinv[c] * (z[c,:] + sum_{e->c} z[src_e,:]) + b
// 16 threads per node, float4 per thread; pull-based, no fp atomics
__global__ __launch_bounds__(256) void k_agg(
    const float* __restrict__ bias, float* __restrict__ ext_out, int to_ext)
{
    int t = blockIdx.x * blockDim.x + threadIdx.x;
    int node = t >> 4;
    if (node >= N_NODES) return;
    int lane = (t & 15) * 4;

    float4 acc = *(const float4*)(g_z + (size_t)node * DIM + lane); // self-loop
    int s0 = g_off[node];
    int cnt = g_cur[node] - s0;   // actual filled count (== g_cnt if all valid)
    for (int i = 0; i < cnt; ++i) {
        int src = g_src[s0 + i];
        float4 v = *(const float4*)(g_z + (size_t)src * DIM + lane);
        acc.x += v.x; acc.y += v.y; acc.z += v.z; acc.w += v.w;
    }
    float s = g_dinv[node];
    float4 bb = *(const float4*)(bias + lane);
    float4 o = make_float4(fmaf(acc.x, s, bb.x), fmaf(acc.y, s, bb.y),
                           fmaf(acc.z, s, bb.z), fmaf(acc.w, s, bb.w));
    float* out = to_ext ? ext_out : g_h;
    *(float4*)(out + (size_t)node * DIM + lane) = o;
}

// ------------------------------------------------------------------
extern "C" void kernel_launch(void* const* d_in, const int* in_sizes, int n_in,
                              void* d_out, int out_size)
{
    const void*  ei   = d_in[0];
    const float* user = (const float*)d_in[1];
    const float* item = (const float*)d_in[2];
    const float* W1   = (const float*)d_in[3];
    const float* b1   = (const float*)d_in[4];
    const float* W2   = (const float*)d_in[5];
    const float* b2   = (const float*)d_in[6];
    float* out        = (float*)d_out;
    int E = in_sizes[0] / 2;

    int zb = (N_NODES + 255) / 256;
    int eb = (E + 255) / 256;

    // graph prep (every launch; kernels only -> graph-capturable)
    k_detect<<<1, 256>>>((const unsigned int*)ei);
    k_zero<<<zb, 256>>>();
    k_hist<<<eb, 256>>>(ei, E);
    k_scan1<<<NUM_SCAN_BLOCKS, 256>>>();
    k_scan2<<<1, 256>>>();
    k_scan3<<<zb, 256>>>();
    k_fill<<<eb, 256>>>(ei, E);

    int gemm_blocks = N_NODES / 64;                 // 3125
    int agg_blocks  = (N_NODES * 16 + 255) / 256;   // 12500

    // layer 1
    k_gemm<<<gemm_blocks, 256>>>(user, item, 0, W1);
    k_agg<<<agg_blocks, 256>>>(b1, out, 0);         // -> g_h
    // layer 2
    k_gemm<<<gemm_blocks, 256>>>(nullptr, nullptr, 1, W2);
    k_agg<<<agg_blocks, 256>>>(b2, out, 1);         // -> d_out
}